// round 11
// baseline (speedup 1.0000x reference)
#include <cuda_runtime.h>
#include <cuda_fp16.h>

typedef unsigned long long u64;
typedef unsigned int u32;

#define Bsz  512
#define Ssz  2688
#define WEEK 672
#define Hsz  512
#define Gn   32
#define Gm   4
#define NTHR 512
#define K0   576
#define K1   1024

// ---- smem layout (bytes) ----
#define OFF_W1R   0             // 16 tiles x 8KB = 131072
#define OFF_FEATW 131072        // 8192
#define OFF_A     139264        // 3 stages x 24576 (A 16KB + W0 slot 8KB)
#define STAGE_STRIDE 24576
#define OFF_WOUT  212992        // 512 f32
#define OFF_SPRED 215040        // 128 f32
#define OFF_B0    215552        // 64 f32
#define OFF_B1    215808        // 64 f32
#define SMEM_BYTES 216064

// ---------------- persistent device state (no allocation) -------------------
__device__ __half d_W0f[2048 * K0];
__device__ __half d_W1f[2048 * K1];
__device__ __half d_h0[2][Bsz * Hsz];
__device__ __half d_h1[2][Bsz * Hsz];
__device__ float  d_bs0[2048], d_bs1[2048];     // permuted gc' = j*4+g
__device__ unsigned d_barA[Gm], d_barB[Gm];

__device__ __forceinline__ u32 swz(u32 off) { return off ^ ((off >> 3) & 0x70); }
__device__ __forceinline__ float fsig(float x) {
    return __fdividef(1.f, 1.f + __expf(-x));
}
__device__ __forceinline__ float ftanh(float x) {
    float e = __expf(-2.f * x);
    return __fdividef(1.f - e, 1.f + e);
}

__device__ __forceinline__ void ldsm4(u32 a, u32& r0, u32& r1, u32& r2, u32& r3) {
    asm volatile("ldmatrix.sync.aligned.m8n8.x4.shared.b16 {%0,%1,%2,%3}, [%4];"
                 : "=r"(r0), "=r"(r1), "=r"(r2), "=r"(r3) : "r"(a));
}
__device__ __forceinline__ void mma16816(float* d, const u32* a, u32 b0, u32 b1) {
    asm volatile(
        "mma.sync.aligned.m16n8k16.row.col.f32.f16.f16.f32 "
        "{%0,%1,%2,%3}, {%4,%5,%6,%7}, {%8,%9}, {%0,%1,%2,%3};"
        : "+f"(d[0]), "+f"(d[1]), "+f"(d[2]), "+f"(d[3])
        : "r"(a[0]), "r"(a[1]), "r"(a[2]), "r"(a[3]), "r"(b0), "r"(b1));
}
__device__ __forceinline__ void cpa16(u32 dst, const void* src) {
    asm volatile("cp.async.cg.shared.global [%0], [%1], 16;" :: "r"(dst), "l"(src));
}
#define CP_COMMIT() asm volatile("cp.async.commit_group;" ::: "memory")
#define CP_WAIT1()  asm volatile("cp.async.wait_group 1;" ::: "memory")
#define CP_WAIT0()  asm volatile("cp.async.wait_group 0;" ::: "memory")

// ---------------- init --------------------------------------------------------
__global__ void init_all(const float* __restrict__ Wih0, const float* __restrict__ Whh0,
                         const float* __restrict__ bih0, const float* __restrict__ bhh0,
                         const float* __restrict__ Wih1, const float* __restrict__ Whh1,
                         const float* __restrict__ bih1, const float* __restrict__ bhh1) {
    long i0 = (long)blockIdx.x * blockDim.x + threadIdx.x;
    long stride = (long)gridDim.x * blockDim.x;
    for (long i = i0; i < 2048L * K0; i += stride) {
        int gc = (int)(i / K0), k = (int)(i % K0);
        int j = gc >> 2, g = gc & 3, row = g * 512 + j;
        float w = 0.f;
        if (k < 33)       w = Wih0[row * 33 + k];
        else if (k >= 64) w = Whh0[row * 512 + (k - 64)];
        d_W0f[i] = __float2half_rn(w);
    }
    for (long i = i0; i < 2048L * K1; i += stride) {
        int gc = (int)(i / K1), k = (int)(i % K1);
        int j = gc >> 2, g = gc & 3, row = g * 512 + j;
        float w = (k < 512) ? Wih1[row * 512 + k] : Whh1[row * 512 + (k - 512)];
        d_W1f[i] = __float2half_rn(w);
    }
    for (long i = i0; i < 2048; i += stride) {
        int j = (int)(i >> 2), g = (int)(i & 3), row = g * 512 + j;
        d_bs0[i] = bih0[row] + bhh0[row];
        d_bs1[i] = bih1[row] + bhh1[row];
    }
    const __half z = __float2half_rn(0.f);
    for (long i = i0; i < (long)Bsz * Hsz; i += stride) {
        d_h0[0][i] = z; d_h0[1][i] = z; d_h1[0][i] = z; d_h1[1][i] = z;
    }
    if (i0 < Gm) { d_barA[i0] = 0u; d_barB[i0] = 0u; }
}

// ---------------- the persistent kernel --------------------------------------
__global__ void __launch_bounds__(NTHR, 1) run_all(
    const float* __restrict__ x, const float* __restrict__ Wout,
    const float* __restrict__ bout, float* __restrict__ out) {
    extern __shared__ __align__(128) char smem[];
    const int tid = threadIdx.x, wid = tid >> 5, lane = tid & 31;
    const int n = blockIdx.x, mrow = blockIdx.y;
    const int bm = mrow * 128;
    const u32 sb = (u32)__cvta_generic_to_shared(smem);
    const float bout0 = bout[0];

    const int warp_m = (wid >> 2) * 32;          // 4 m-groups of 32 rows
    const int warp_n = (wid & 3) * 16;           // 4 n-groups of 16 gc
    const u32 aswz0 = swz((u32)((warp_m + (lane & 7) + ((lane >> 3) & 1) * 8) * 128
                                + (lane >> 4) * 16));
    const u32 bswz0 = swz((u32)((warp_n + (lane & 7) + (lane >> 4) * 8) * 128
                                + ((lane >> 3) & 1) * 16));
    const int jl0 = (warp_n >> 2) + ((lane & 3) >> 1);

    // precomputed staging offsets (registers)
    const int c8 = tid & 7, r0 = tid >> 3;        // r0: 0..63
    u32 soffA[2]; int goffA[2];
#pragma unroll
    for (int q = 0; q < 2; q++) {
        int r = r0 + q * 64;
        soffA[q] = swz((u32)(r * 128 + c8 * 16));
        goffA[q] = (bm + r) * Hsz + c8 * 8;
    }
    const u32 soffW = swz((u32)(r0 * 128 + c8 * 16));
    const int goffW = (n * 64 + r0) * K0 + c8 * 8;

    float* sWo = reinterpret_cast<float*>(smem + OFF_WOUT);
    float* sPred = reinterpret_cast<float*>(smem + OFF_SPRED);
    float* sB0 = reinterpret_cast<float*>(smem + OFF_B0);
    float* sB1 = reinterpret_cast<float*>(smem + OFF_B1);
    if (tid < 512) sWo[tid] = Wout[tid];
    if (tid < 64)  sB0[tid] = d_bs0[n * 64 + tid];
    else if (tid < 128) sB1[tid - 64] = d_bs1[n * 64 + tid - 64];

    // ---- resident weights: W1 (16 tiles) + feature W0 tile ----
#pragma unroll
    for (int q = 0; q < 16; q++) {
        int u = tid + q * NTHR;
        int tile = u >> 9, w = u & 511, rr = w >> 3, cc = w & 7;
        cpa16(sb + OFF_W1R + tile * 8192 + swz((u32)(rr * 128 + cc * 16)),
              d_W1f + (long)(n * 64 + rr) * K1 + tile * 64 + cc * 8);
    }
    cpa16(sb + OFF_FEATW + soffW, d_W0f + goffW);
    CP_COMMIT(); CP_WAIT0();
    __syncthreads();

    float acc[2][2][4];
    float c0r[2][2], c1r[2][2];
#pragma unroll
    for (int mf = 0; mf < 2; mf++)
#pragma unroll
        for (int nf = 0; nf < 2; nf++) { c0r[mf][nf] = 0.f; c1r[mf][nf] = 0.f; }

    auto stageChunk = [&](int c, int tt) {
        if (c == 8) { CP_COMMIT(); return; }
        u32 base = sb + OFF_A + ((c + tt) % 3) * STAGE_STRIDE;
        const __half* src;
        int kc;
        if (c < 8)       { src = d_h0[tt & 1];       kc = c * 64; }
        else if (c < 17) { src = d_h1[tt & 1];       kc = (c - 9) * 64; }
        else             { src = d_h0[(tt & 1) ^ 1]; kc = (c - 17) * 64; }
#pragma unroll
        for (int q = 0; q < 2; q++)
            cpa16(base + soffA[q], src + kc + goffA[q]);
        if (c < 8)
            cpa16(base + 16384 + soffW, d_W0f + (c + 1) * 64 + goffW);
        CP_COMMIT();
    };
    auto mma_tiles = [&](u32 aB, u32 wB) {
#pragma unroll
        for (int kkl = 0; kkl < 4; kkl++) {
            const u32 a_sw = aswz0 ^ (u32)(kkl * 32);
            const u32 b_sw = bswz0 ^ (u32)(kkl * 32);
            u32 ah[2][4], bh[4];
#pragma unroll
            for (int mf = 0; mf < 2; mf++)
                ldsm4(aB + a_sw + mf * 2048, ah[mf][0], ah[mf][1], ah[mf][2], ah[mf][3]);
            ldsm4(wB + b_sw, bh[0], bh[1], bh[2], bh[3]);
#pragma unroll
            for (int mf = 0; mf < 2; mf++)
#pragma unroll
                for (int nf = 0; nf < 2; nf++)
                    mma16816(&acc[mf][nf][0], ah[mf], bh[nf * 2], bh[nf * 2 + 1]);
        }
    };
    auto epilogue = [&](float cre[2][2], const float* bs, __half* __restrict__ hdst) {
        const bool od = (lane & 1);
        const int rbase = warp_m + (lane >> 2) + (od ? 8 : 0);
#pragma unroll
        for (int mf = 0; mf < 2; mf++)
#pragma unroll
            for (int nf = 0; nf < 2; nf++) {
                float4 bia = *reinterpret_cast<const float4*>(&bs[(jl0 + nf * 2) * 4]);
                float d0 = acc[mf][nf][0], d1 = acc[mf][nf][1];
                float d2 = acc[mf][nf][2], d3 = acc[mf][nf][3];
                float v1 = __shfl_xor_sync(0xffffffffu, od ? d0 : d2, 1);
                float v2 = __shfl_xor_sync(0xffffffffu, od ? d1 : d3, 1);
                float gi = od ? v1 : d0;
                float gf = od ? v2 : d1;
                float gg = od ? d2 : v1;
                float go = od ? d3 : v2;
                float iv = fsig(gi + bia.x);
                float fv = fsig(gf + bia.y);
                float gv = ftanh(gg + bia.z);
                float ov = fsig(go + bia.w);
                float cn = fv * cre[mf][nf] + iv * gv;
                cre[mf][nf] = cn;
                int row = rbase + mf * 16;
                int col = n * 16 + jl0 + nf * 2;
                hdst[(long)(bm + row) * Hsz + col] = __float2half_rn(ov * ftanh(cn));
            }
    };
    auto barwait = [&](unsigned* ctr, unsigned target) {
        if (tid == 0) {
            unsigned cur;
            do {
                asm volatile("ld.acquire.gpu.u32 %0, [%1];"
                             : "=r"(cur) : "l"(ctr) : "memory");
            } while (cur < target);
        }
        __syncthreads();
    };
    auto arrive = [&](unsigned* ctr) {
        __syncthreads();
        if (tid == 0) {
            unsigned old, one = 1u;
            asm volatile("atom.release.gpu.add.u32 %0, [%1], %2;"
                         : "=r"(old) : "l"(ctr), "r"(one) : "memory");
        }
    };
    auto lazy_out = [&](const __half* __restrict__ h1s, int tw) {
        if (wid < 4) {
            int row = n * 4 + wid;
            const uint4* hp = reinterpret_cast<const uint4*>(h1s + (long)(bm + row) * Hsz);
            float sv = 0.f;
#pragma unroll
            for (int h8 = 0; h8 < 2; h8++) {
                uint4 vv = hp[lane * 2 + h8];
                const __half2* pp = reinterpret_cast<const __half2*>(&vv);
#pragma unroll
                for (int q = 0; q < 4; q++) {
                    float2 f2 = __half22float2(pp[q]);
                    int base = lane * 16 + h8 * 8 + q * 2;
                    sv += f2.x * sWo[base] + f2.y * sWo[base + 1];
                }
            }
#pragma unroll
            for (int o = 16; o > 0; o >>= 1) sv += __shfl_down_sync(0xffffffffu, sv, o);
            if (lane == 0) out[(long)(bm + row) * Ssz + tw] = sv + bout0;
        }
    };

    // prologue: stage chunks 0,1 of step 0
    stageChunk(0, 0);
    stageChunk(1, 0);

#pragma unroll 1
    for (int t = 0; t < Ssz; t++) {
        const bool fb = (((t / WEEK) & 1) == 1);
        const __half* h1s = d_h1[t & 1];
        __half* h0d = d_h0[(t & 1) ^ 1];
        __half* h1d = d_h1[(t & 1) ^ 1];

#pragma unroll 1
        for (int g = 0; g < 25; g++) {
            const u32 aB = sb + OFF_A + ((g + t) % 3) * STAGE_STRIDE;
            CP_WAIT1();
            if (g == 8) {
                if (fb) {   // predictions for step t-1 (h1s ready: barB waited at g==7)
                    int r = tid >> 2, hf = tid & 3;        // 4 threads per row
                    const uint4* hp = reinterpret_cast<const uint4*>(
                        h1s + (long)(bm + r) * Hsz) + hf * 16;
                    float sv = 0.f;
#pragma unroll 8
                    for (int i = 0; i < 16; i++) {
                        uint4 vv = hp[i];
                        const __half2* pp = reinterpret_cast<const __half2*>(&vv);
#pragma unroll
                        for (int q = 0; q < 4; q++) {
                            float2 f2 = __half22float2(pp[q]);
                            int base = hf * 128 + i * 8 + q * 2;
                            sv += f2.x * sWo[base] + f2.y * sWo[base + 1];
                        }
                    }
                    sv += __shfl_xor_sync(0xffffffffu, sv, 1);
                    sv += __shfl_xor_sync(0xffffffffu, sv, 2);
                    if (hf == 0) {
                        float val = sv + bout0;
                        sPred[r] = val;
                        if ((r >> 2) == n) out[(long)(bm + r) * Ssz + (t - 1)] = val;
                    }
                    __syncthreads();
                }
                // stage features (STS) into this chunk's slot
#pragma unroll
                for (int q = 0; q < 2; q++) {
                    int r = r0 + q * 64;
                    __align__(16) __half hv[8];
                    if (c8 < 4) {
                        const float* xr = x + ((long)(bm + r) * Ssz + t) * 32 + c8 * 8;
#pragma unroll
                        for (int i = 0; i < 8; i++) {
                            float v = xr[i];
                            if (c8 == 0 && i == 0 && fb) v = sPred[r];
                            hv[i] = __float2half_rn(v);
                        }
                    } else {
#pragma unroll
                        for (int i = 0; i < 8; i++) hv[i] = __ushort_as_half(0);
                        if (c8 == 4) hv[0] = __float2half_rn(fb ? 1.f : 0.f);
                    }
                    *reinterpret_cast<uint4*>(smem + (aB - sb) + soffA[q]) =
                        *reinterpret_cast<uint4*>(hv);
                }
            }
            __syncthreads();

            if (g == 0 || g == 9) {
#pragma unroll
                for (int mf = 0; mf < 2; mf++)
#pragma unroll
                    for (int nf = 0; nf < 2; nf++)
#pragma unroll
                        for (int q = 0; q < 4; q++) acc[mf][nf][q] = 0.f;
            }

            const u32 wB = (g < 8)   ? aB + 16384
                         : (g == 8)  ? sb + OFF_FEATW
                         : (g <= 16) ? sb + OFF_W1R + (g - 1) * 8192
                                     : sb + OFF_W1R + (g - 17) * 8192;
            mma_tiles(aB, wB);

            if (g == 7 && t > 0) {
                barwait(&d_barB[mrow], 32u * (u32)t);
                if (!fb) lazy_out(h1s, t - 1);
            }
            if (g == 15) barwait(&d_barA[mrow], 32u * (u32)(t + 1));

            if (g < 23)       stageChunk(g + 2, t);
            else if (g == 23) stageChunk(0, t + 1);
            else              stageChunk(1, t + 1);

            if (g == 8) {
                epilogue(c0r, sB0, h0d);
                arrive(&d_barA[mrow]);
            }
            if (g == 24) {
                epilogue(c1r, sB1, h1d);
                arrive(&d_barB[mrow]);
            }
        }
    }

    // final output column (t = Ssz-1)
    barwait(&d_barB[mrow], 32u * (u32)Ssz);
    lazy_out(d_h1[Ssz & 1], Ssz - 1);
}

// ---------------- launch ------------------------------------------------------
extern "C" void kernel_launch(void* const* d_in, const int* in_sizes, int n_in,
                              void* d_out, int out_size) {
    const float* x    = (const float*)d_in[0];
    const float* Wih0 = (const float*)d_in[1];
    const float* Whh0 = (const float*)d_in[2];
    const float* bih0 = (const float*)d_in[3];
    const float* bhh0 = (const float*)d_in[4];
    const float* Wih1 = (const float*)d_in[5];
    const float* Whh1 = (const float*)d_in[6];
    const float* bih1 = (const float*)d_in[7];
    const float* bhh1 = (const float*)d_in[8];
    const float* Wout = (const float*)d_in[9];
    const float* bout = (const float*)d_in[10];
    float* out = (float*)d_out;

    cudaFuncSetAttribute(run_all, cudaFuncAttributeMaxDynamicSharedMemorySize, SMEM_BYTES);
    init_all<<<1024, 256>>>(Wih0, Whh0, bih0, bhh0, Wih1, Whh1, bih1, bhh1);
    run_all<<<dim3(Gn, Gm), NTHR, SMEM_BYTES>>>(x, Wout, bout, out);
}

// round 12
// speedup vs baseline: 1.0258x; 1.0258x over previous
#include <cuda_runtime.h>
#include <cuda_fp16.h>

typedef unsigned long long u64;
typedef unsigned int u32;

#define Bsz  512
#define Ssz  2688
#define WEEK 672
#define Hsz  512
#define Gn   32
#define Gm   4
#define NTHR 256
#define K0   576
#define K1   1024

// ---- smem layout (bytes) ----
#define OFF_W1R   0             // 16 tiles x 8KB = 131072 (resident)
#define OFF_A     131072        // 4 A slots x 16384 = 65536
#define OFF_W0S   196608        // 4 W0 stream slots x 8192 = 32768
#define OFF_WOUT  229376        // 512 f32 = 2048
#define OFF_SPRED 231424        // 128 f32 = 512
#define SMEM_BYTES 231936

// ---------------- persistent device state (no allocation) -------------------
__device__ __half d_W0f[2048 * K0];
__device__ __half d_W1f[2048 * K1];
__device__ __half d_h0[2][Bsz * Hsz];
__device__ __half d_h1[2][Bsz * Hsz];
__device__ float  d_bs0[2048], d_bs1[2048];     // permuted gc' = j*4+g
__device__ unsigned d_barA[Gm], d_barB[Gm];

__device__ __forceinline__ u32 swz(u32 off) { return off ^ ((off >> 3) & 0x70); }
__device__ __forceinline__ float fsig(float x) {
    return __fdividef(1.f, 1.f + __expf(-x));
}
__device__ __forceinline__ float ftanh(float x) {
    float e = __expf(-2.f * x);
    return __fdividef(1.f - e, 1.f + e);
}

__device__ __forceinline__ void ldsm4(u32 a, u32& r0, u32& r1, u32& r2, u32& r3) {
    asm volatile("ldmatrix.sync.aligned.m8n8.x4.shared.b16 {%0,%1,%2,%3}, [%4];"
                 : "=r"(r0), "=r"(r1), "=r"(r2), "=r"(r3) : "r"(a));
}
__device__ __forceinline__ void mma16816(float* d, const u32* a, u32 b0, u32 b1) {
    asm volatile(
        "mma.sync.aligned.m16n8k16.row.col.f32.f16.f16.f32 "
        "{%0,%1,%2,%3}, {%4,%5,%6,%7}, {%8,%9}, {%0,%1,%2,%3};"
        : "+f"(d[0]), "+f"(d[1]), "+f"(d[2]), "+f"(d[3])
        : "r"(a[0]), "r"(a[1]), "r"(a[2]), "r"(a[3]), "r"(b0), "r"(b1));
}
__device__ __forceinline__ void cpa16(u32 dst, const void* src) {
    asm volatile("cp.async.cg.shared.global [%0], [%1], 16;" :: "r"(dst), "l"(src));
}
#define CP_COMMIT() asm volatile("cp.async.commit_group;" ::: "memory")
#define CP_WAIT2()  asm volatile("cp.async.wait_group 2;" ::: "memory")
#define CP_WAIT0()  asm volatile("cp.async.wait_group 0;" ::: "memory")

// ---------------- init --------------------------------------------------------
__global__ void init_all(const float* __restrict__ Wih0, const float* __restrict__ Whh0,
                         const float* __restrict__ bih0, const float* __restrict__ bhh0,
                         const float* __restrict__ Wih1, const float* __restrict__ Whh1,
                         const float* __restrict__ bih1, const float* __restrict__ bhh1) {
    long i0 = (long)blockIdx.x * blockDim.x + threadIdx.x;
    long stride = (long)gridDim.x * blockDim.x;
    for (long i = i0; i < 2048L * K0; i += stride) {
        int gc = (int)(i / K0), k = (int)(i % K0);
        int j = gc >> 2, g = gc & 3, row = g * 512 + j;
        float w = 0.f;
        if (k < 33)       w = Wih0[row * 33 + k];
        else if (k >= 64) w = Whh0[row * 512 + (k - 64)];
        d_W0f[i] = __float2half_rn(w);
    }
    for (long i = i0; i < 2048L * K1; i += stride) {
        int gc = (int)(i / K1), k = (int)(i % K1);
        int j = gc >> 2, g = gc & 3, row = g * 512 + j;
        float w = (k < 512) ? Wih1[row * 512 + k] : Whh1[row * 512 + (k - 512)];
        d_W1f[i] = __float2half_rn(w);
    }
    for (long i = i0; i < 2048; i += stride) {
        int j = (int)(i >> 2), g = (int)(i & 3), row = g * 512 + j;
        d_bs0[i] = bih0[row] + bhh0[row];
        d_bs1[i] = bih1[row] + bhh1[row];
    }
    const __half z = __float2half_rn(0.f);
    for (long i = i0; i < (long)Bsz * Hsz; i += stride) {
        d_h0[0][i] = z; d_h0[1][i] = z; d_h1[0][i] = z; d_h1[1][i] = z;
    }
    if (i0 < Gm) { d_barA[i0] = 0u; d_barB[i0] = 0u; }
}

// ---------------- the persistent kernel --------------------------------------
__global__ void __launch_bounds__(NTHR, 1) run_all(
    const float* __restrict__ x, const float* __restrict__ Wout,
    const float* __restrict__ bout, float* __restrict__ out) {
    extern __shared__ __align__(128) char smem[];
    const int tid = threadIdx.x, wid = tid >> 5, lane = tid & 31;
    const int n = blockIdx.x, mrow = blockIdx.y;
    const int bm = mrow * 128;
    const u32 sb = (u32)__cvta_generic_to_shared(smem);
    const float bout0 = bout[0];

    const int warp_m = (wid >> 2) * 64;          // 2 m-groups
    const int warp_n = (wid & 3) * 16;           // 4 n-groups of 16 gc
    const u32 aswz0 = swz((u32)((warp_m + (lane & 7) + ((lane >> 3) & 1) * 8) * 128
                                + (lane >> 4) * 16));
    const u32 bswz0 = swz((u32)((warp_n + (lane & 7) + (lane >> 4) * 8) * 128
                                + ((lane >> 3) & 1) * 16));
    const int jl0 = (warp_n >> 2) + ((lane & 3) >> 1);
    float4 bia0[2], bia1[2];
    bia0[0] = *reinterpret_cast<const float4*>(&d_bs0[n * 64 + jl0 * 4]);
    bia0[1] = *reinterpret_cast<const float4*>(&d_bs0[n * 64 + (jl0 + 2) * 4]);
    bia1[0] = *reinterpret_cast<const float4*>(&d_bs1[n * 64 + jl0 * 4]);
    bia1[1] = *reinterpret_cast<const float4*>(&d_bs1[n * 64 + (jl0 + 2) * 4]);

    // precomputed staging offsets (registers)
    const int c8 = tid & 7, r0 = tid >> 3;
    u32 soffA[4]; int goffA[4];
    u32 soffW[2]; int goffW[2];
#pragma unroll
    for (int q = 0; q < 4; q++) {
        int r = r0 + q * 32;
        soffA[q] = swz((u32)(r * 128 + c8 * 16));
        goffA[q] = (bm + r) * Hsz + c8 * 8;
    }
#pragma unroll
    for (int q = 0; q < 2; q++) {
        int rr = r0 + q * 32;
        soffW[q] = swz((u32)(rr * 128 + c8 * 16));
        goffW[q] = (n * 64 + rr) * K0 + c8 * 8;
    }

    float* sWo = reinterpret_cast<float*>(smem + OFF_WOUT);
    float* sPred = reinterpret_cast<float*>(smem + OFF_SPRED);
    for (int i = tid; i < 512; i += NTHR) sWo[i] = Wout[i];

    // ---- resident W1 (16 tiles) ----
#pragma unroll
    for (int q = 0; q < 32; q++) {
        int u = tid + q * NTHR;
        int tile = u >> 9, w = u & 511, rr = w >> 3, cc = w & 7;
        cpa16(sb + OFF_W1R + tile * 8192 + swz((u32)(rr * 128 + cc * 16)),
              d_W1f + (long)(n * 64 + rr) * K1 + tile * 64 + cc * 8);
    }
    CP_COMMIT(); CP_WAIT0();
    __syncthreads();

    float acc[4][2][4];
    float c0r[4][2], c1r[4][2];
#pragma unroll
    for (int mf = 0; mf < 4; mf++)
#pragma unroll
        for (int nf = 0; nf < 2; nf++) { c0r[mf][nf] = 0.f; c1r[mf][nf] = 0.f; }

    // stage absolute chunk cid (= t*25 + c) into A/W0 ring slot cid&3.
    // chunk c: 0..7 = h0_old (+W0 tile c+1) ; 8 = feature (A via STS, W0 tile 0)
    //          9..16 = h1_old ; 17..24 = h0_new
    auto stageCid = [&](int cid) {
        int c = cid % 25, tt = cid / 25;
        u32 slot = (u32)(cid & 3);
        if (c != 8) {
            u32 baseA = sb + OFF_A + slot * 16384;
            const __half* src;
            int kc;
            if (c < 8)       { src = d_h0[tt & 1];       kc = c * 64; }
            else if (c < 17) { src = d_h1[tt & 1];       kc = (c - 9) * 64; }
            else             { src = d_h0[(tt & 1) ^ 1]; kc = (c - 17) * 64; }
#pragma unroll
            for (int q = 0; q < 4; q++)
                cpa16(baseA + soffA[q], src + kc + goffA[q]);
        }
        if (c <= 8) {
            int wt = (c == 8) ? 0 : (c + 1);
            u32 baseW = sb + OFF_W0S + slot * 8192;
#pragma unroll
            for (int q = 0; q < 2; q++)
                cpa16(baseW + soffW[q], d_W0f + wt * 64 + goffW[q]);
        }
        CP_COMMIT();
    };
    auto mma_tiles = [&](u32 aB, u32 wB) {
#pragma unroll
        for (int kkl = 0; kkl < 4; kkl++) {
            const u32 a_sw = aswz0 ^ (u32)(kkl * 32);
            const u32 b_sw = bswz0 ^ (u32)(kkl * 32);
            u32 ah[4][4], bh[4];
#pragma unroll
            for (int mf = 0; mf < 4; mf++)
                ldsm4(aB + a_sw + mf * 2048, ah[mf][0], ah[mf][1], ah[mf][2], ah[mf][3]);
            ldsm4(wB + b_sw, bh[0], bh[1], bh[2], bh[3]);
#pragma unroll
            for (int mf = 0; mf < 4; mf++)
#pragma unroll
                for (int nf = 0; nf < 2; nf++)
                    mma16816(&acc[mf][nf][0], ah[mf], bh[nf * 2], bh[nf * 2 + 1]);
        }
    };
    auto epilogue = [&](float cre[4][2], const float4* bia, __half* __restrict__ hdst) {
        const bool od = (lane & 1);
        const int rbase = warp_m + (lane >> 2) + (od ? 8 : 0);
#pragma unroll
        for (int mf = 0; mf < 4; mf++)
#pragma unroll
            for (int nf = 0; nf < 2; nf++) {
                float d0 = acc[mf][nf][0], d1 = acc[mf][nf][1];
                float d2 = acc[mf][nf][2], d3 = acc[mf][nf][3];
                float v1 = __shfl_xor_sync(0xffffffffu, od ? d0 : d2, 1);
                float v2 = __shfl_xor_sync(0xffffffffu, od ? d1 : d3, 1);
                float gi = od ? v1 : d0;
                float gf = od ? v2 : d1;
                float gg = od ? d2 : v1;
                float go = od ? d3 : v2;
                float iv = fsig(gi + bia[nf].x);
                float fv = fsig(gf + bia[nf].y);
                float gv = ftanh(gg + bia[nf].z);
                float ov = fsig(go + bia[nf].w);
                float cn = fv * cre[mf][nf] + iv * gv;
                cre[mf][nf] = cn;
                int row = rbase + mf * 16;
                int col = n * 16 + jl0 + nf * 2;
                hdst[(long)(bm + row) * Hsz + col] = __float2half_rn(ov * ftanh(cn));
            }
    };
    auto barwait = [&](unsigned* ctr, unsigned target) {
        if (tid == 0) {
            unsigned cur;
            do {
                asm volatile("ld.acquire.gpu.u32 %0, [%1];"
                             : "=r"(cur) : "l"(ctr) : "memory");
            } while (cur < target);
        }
        __syncthreads();
    };
    auto arrive = [&](unsigned* ctr) {
        __syncthreads();
        if (tid == 0) {
            unsigned old, one = 1u;
            asm volatile("atom.release.gpu.add.u32 %0, [%1], %2;"
                         : "=r"(old) : "l"(ctr), "r"(one) : "memory");
        }
    };
    auto lazy_out = [&](const __half* __restrict__ h1s, int tw) {
        if (wid < 4) {
            int row = n * 4 + wid;
            const uint4* hp = reinterpret_cast<const uint4*>(h1s + (long)(bm + row) * Hsz);
            float sv = 0.f;
#pragma unroll
            for (int h8 = 0; h8 < 2; h8++) {
                uint4 vv = hp[lane * 2 + h8];
                const __half2* pp = reinterpret_cast<const __half2*>(&vv);
#pragma unroll
                for (int q = 0; q < 4; q++) {
                    float2 f2 = __half22float2(pp[q]);
                    int base = lane * 16 + h8 * 8 + q * 2;
                    sv += f2.x * sWo[base] + f2.y * sWo[base + 1];
                }
            }
#pragma unroll
            for (int o = 16; o > 0; o >>= 1) sv += __shfl_down_sync(0xffffffffu, sv, o);
            if (lane == 0) out[(long)(bm + row) * Ssz + tw] = sv + bout0;
        }
    };

    // prologue: stage chunks 0,1,2 of step 0 (3 groups in flight)
    stageCid(0);
    stageCid(1);
    stageCid(2);

#pragma unroll 1
    for (int t = 0; t < Ssz; t++) {
        const bool fb = (((t / WEEK) & 1) == 1);
        const __half* h1s = d_h1[t & 1];
        __half* h0d = d_h0[(t & 1) ^ 1];
        __half* h1d = d_h1[(t & 1) ^ 1];
        const int cid0 = t * 25;

#pragma unroll 1
        for (int g = 0; g < 25; g++) {
            const int cid = cid0 + g;
            const u32 aB = sb + OFF_A + (u32)(cid & 3) * 16384;
            CP_WAIT2();
            if (g == 8) {
                if (fb) {   // predictions for step t-1 (h1s ready: barB waited at g==6)
                    int r = tid >> 1, hf = tid & 1;
                    const uint4* hp = reinterpret_cast<const uint4*>(
                        h1s + (long)(bm + r) * Hsz) + hf * 32;
                    float sv = 0.f;
#pragma unroll 8
                    for (int i = 0; i < 32; i++) {
                        uint4 vv = hp[i];
                        const __half2* pp = reinterpret_cast<const __half2*>(&vv);
#pragma unroll
                        for (int q = 0; q < 4; q++) {
                            float2 f2 = __half22float2(pp[q]);
                            int base = hf * 256 + i * 8 + q * 2;
                            sv += f2.x * sWo[base] + f2.y * sWo[base + 1];
                        }
                    }
                    sv += __shfl_xor_sync(0xffffffffu, sv, 1);
                    if (hf == 0) {
                        float val = sv + bout0;
                        sPred[r] = val;
                        if ((r >> 2) == n) out[(long)(bm + r) * Ssz + (t - 1)] = val;
                    }
                    __syncthreads();
                }
                // stage features (STS) into this chunk's A slot
#pragma unroll
                for (int q = 0; q < 4; q++) {
                    int r = r0 + q * 32;
                    __align__(16) __half hv[8];
                    if (c8 < 4) {
                        const float* xr = x + ((long)(bm + r) * Ssz + t) * 32 + c8 * 8;
#pragma unroll
                        for (int i = 0; i < 8; i++) {
                            float v = xr[i];
                            if (c8 == 0 && i == 0 && fb) v = sPred[r];
                            hv[i] = __float2half_rn(v);
                        }
                    } else {
#pragma unroll
                        for (int i = 0; i < 8; i++) hv[i] = __ushort_as_half(0);
                        if (c8 == 4) hv[0] = __float2half_rn(fb ? 1.f : 0.f);
                    }
                    *reinterpret_cast<uint4*>(smem + (aB - sb) + soffA[q]) =
                        *reinterpret_cast<uint4*>(hv);
                }
            }
            __syncthreads();

            if (g == 0 || g == 9) {
#pragma unroll
                for (int mf = 0; mf < 4; mf++)
#pragma unroll
                    for (int nf = 0; nf < 2; nf++)
#pragma unroll
                        for (int q = 0; q < 4; q++) acc[mf][nf][q] = 0.f;
            }

            const u32 wB = (g <= 8)  ? sb + OFF_W0S + (u32)(cid & 3) * 8192
                         : (g <= 16) ? sb + OFF_W1R + (g - 1) * 8192
                                     : sb + OFF_W1R + (g - 17) * 8192;
            mma_tiles(aB, wB);

            if (g == 6 && t > 0) {
                barwait(&d_barB[mrow], 32u * (u32)t);
                if (!fb) lazy_out(h1s, t - 1);
            }
            if (g == 14) barwait(&d_barA[mrow], 32u * (u32)(t + 1));

            stageCid(cid + 3);

            if (g == 8) {
                epilogue(c0r, bia0, h0d);
                arrive(&d_barA[mrow]);
            }
            if (g == 24) {
                epilogue(c1r, bia1, h1d);
                arrive(&d_barB[mrow]);
            }
        }
    }

    // final output column (t = Ssz-1)
    CP_WAIT0();
    barwait(&d_barB[mrow], 32u * (u32)Ssz);
    lazy_out(d_h1[Ssz & 1], Ssz - 1);
}

// ---------------- launch ------------------------------------------------------
extern "C" void kernel_launch(void* const* d_in, const int* in_sizes, int n_in,
                              void* d_out, int out_size) {
    const float* x    = (const float*)d_in[0];
    const float* Wih0 = (const float*)d_in[1];
    const float* Whh0 = (const float*)d_in[2];
    const float* bih0 = (const float*)d_in[3];
    const float* bhh0 = (const float*)d_in[4];
    const float* Wih1 = (const float*)d_in[5];
    const float* Whh1 = (const float*)d_in[6];
    const float* bih1 = (const float*)d_in[7];
    const float* bhh1 = (const float*)d_in[8];
    const float* Wout = (const float*)d_in[9];
    const float* bout = (const float*)d_in[10];
    float* out = (float*)d_out;

    cudaFuncSetAttribute(run_all, cudaFuncAttributeMaxDynamicSharedMemorySize, SMEM_BYTES);
    init_all<<<1024, 256>>>(Wih0, Whh0, bih0, bhh0, Wih1, Whh1, bih1, bhh1);
    run_all<<<dim3(Gn, Gm), NTHR, SMEM_BYTES>>>(x, Wout, bout, out);
}

// round 13
// speedup vs baseline: 1.0923x; 1.0648x over previous
#include <cuda_runtime.h>
#include <cuda_fp16.h>

typedef unsigned long long u64;
typedef unsigned int u32;

#define Bsz  512
#define Ssz  2688
#define WEEK 672
#define Hsz  512
#define Gn   32
#define Gm   4
#define NTHR 256
#define K0   576
#define K1   1024

// ---- smem layout (bytes) ----
#define OFF_W1R   0             // 16 tiles x 8KB = 131072 (resident)
#define OFF_A     131072        // 4 A slots x 16384 = 65536
#define OFF_W0S   196608        // 4 W0 stream slots x 8192 = 32768
#define OFF_WOUT  229376        // 512 f32 = 2048
#define OFF_SPRED 231424        // 128 f32 = 512
#define SMEM_BYTES 231936

// ---------------- persistent device state (no allocation) -------------------
__device__ __half d_W0f[2048 * K0];
__device__ __half d_W1f[2048 * K1];
__device__ __half d_h0[2][Bsz * Hsz];
__device__ __half d_h1[2][Bsz * Hsz];
__device__ float  d_bs0[2048], d_bs1[2048];     // permuted gc' = j*4+g
__device__ unsigned d_barA[Gm], d_barB[Gm];

__device__ __forceinline__ u32 swz(u32 off) { return off ^ ((off >> 3) & 0x70); }
__device__ __forceinline__ float fsig(float x) {
    return __fdividef(1.f, 1.f + __expf(-x));
}
__device__ __forceinline__ float ftanh(float x) {
    float e = __expf(-2.f * x);
    return __fdividef(1.f - e, 1.f + e);
}

__device__ __forceinline__ void ldsm4(u32 a, u32& r0, u32& r1, u32& r2, u32& r3) {
    asm volatile("ldmatrix.sync.aligned.m8n8.x4.shared.b16 {%0,%1,%2,%3}, [%4];"
                 : "=r"(r0), "=r"(r1), "=r"(r2), "=r"(r3) : "r"(a));
}
__device__ __forceinline__ void mma16816(float* d, const u32* a, u32 b0, u32 b1) {
    asm volatile(
        "mma.sync.aligned.m16n8k16.row.col.f32.f16.f16.f32 "
        "{%0,%1,%2,%3}, {%4,%5,%6,%7}, {%8,%9}, {%0,%1,%2,%3};"
        : "+f"(d[0]), "+f"(d[1]), "+f"(d[2]), "+f"(d[3])
        : "r"(a[0]), "r"(a[1]), "r"(a[2]), "r"(a[3]), "r"(b0), "r"(b1));
}
__device__ __forceinline__ void cpa16(u32 dst, const void* src) {
    asm volatile("cp.async.cg.shared.global [%0], [%1], 16;" :: "r"(dst), "l"(src));
}
#define CP_COMMIT() asm volatile("cp.async.commit_group;" ::: "memory")
#define CP_WAIT2()  asm volatile("cp.async.wait_group 2;" ::: "memory")
#define CP_WAIT0()  asm volatile("cp.async.wait_group 0;" ::: "memory")

// ---------------- init --------------------------------------------------------
__global__ void init_all(const float* __restrict__ Wih0, const float* __restrict__ Whh0,
                         const float* __restrict__ bih0, const float* __restrict__ bhh0,
                         const float* __restrict__ Wih1, const float* __restrict__ Whh1,
                         const float* __restrict__ bih1, const float* __restrict__ bhh1) {
    long i0 = (long)blockIdx.x * blockDim.x + threadIdx.x;
    long stride = (long)gridDim.x * blockDim.x;
    for (long i = i0; i < 2048L * K0; i += stride) {
        int gc = (int)(i / K0), k = (int)(i % K0);
        int j = gc >> 2, g = gc & 3, row = g * 512 + j;
        float w = 0.f;
        if (k < 33)       w = Wih0[row * 33 + k];
        else if (k >= 64) w = Whh0[row * 512 + (k - 64)];
        d_W0f[i] = __float2half_rn(w);
    }
    for (long i = i0; i < 2048L * K1; i += stride) {
        int gc = (int)(i / K1), k = (int)(i % K1);
        int j = gc >> 2, g = gc & 3, row = g * 512 + j;
        float w = (k < 512) ? Wih1[row * 512 + k] : Whh1[row * 512 + (k - 512)];
        d_W1f[i] = __float2half_rn(w);
    }
    for (long i = i0; i < 2048; i += stride) {
        int j = (int)(i >> 2), g = (int)(i & 3), row = g * 512 + j;
        d_bs0[i] = bih0[row] + bhh0[row];
        d_bs1[i] = bih1[row] + bhh1[row];
    }
    const __half z = __float2half_rn(0.f);
    for (long i = i0; i < (long)Bsz * Hsz; i += stride) {
        d_h0[0][i] = z; d_h0[1][i] = z; d_h1[0][i] = z; d_h1[1][i] = z;
    }
    if (i0 < Gm) { d_barA[i0] = 0u; d_barB[i0] = 0u; }
}

// ---------------- the persistent kernel --------------------------------------
__global__ void __launch_bounds__(NTHR, 1) run_all(
    const float* __restrict__ x, const float* __restrict__ Wout,
    const float* __restrict__ bout, float* __restrict__ out) {
    extern __shared__ __align__(128) char smem[];
    const int tid = threadIdx.x, wid = tid >> 5, lane = tid & 31;
    const int n = blockIdx.x, mrow = blockIdx.y;
    const int bm = mrow * 128;
    const u32 sb = (u32)__cvta_generic_to_shared(smem);
    const float bout0 = bout[0];

    const int warp_m = (wid >> 1) * 32;          // 4 m-groups of 32 rows
    const int warp_n = (wid & 1) * 32;           // 2 n-groups of 32 gc
    const u32 aswz0 = swz((u32)((warp_m + (lane & 7) + ((lane >> 3) & 1) * 8) * 128
                                + (lane >> 4) * 16));
    const u32 bswz0 = swz((u32)((warp_n + (lane & 7) + (lane >> 4) * 8) * 128
                                + ((lane >> 3) & 1) * 16));
    const int jl0 = (warp_n >> 2) + ((lane & 3) >> 1);   // local j for nf=0
    float4 bia0[4], bia1[4];
#pragma unroll
    for (int nf = 0; nf < 4; nf++) {
        bia0[nf] = *reinterpret_cast<const float4*>(&d_bs0[n * 64 + (jl0 + nf * 2) * 4]);
        bia1[nf] = *reinterpret_cast<const float4*>(&d_bs1[n * 64 + (jl0 + nf * 2) * 4]);
    }

    // precomputed staging offsets (registers)
    const int c8 = tid & 7, r0 = tid >> 3;
    u32 soffA[4]; int goffA[4];
    u32 soffW[2]; int goffW[2];
#pragma unroll
    for (int q = 0; q < 4; q++) {
        int r = r0 + q * 32;
        soffA[q] = swz((u32)(r * 128 + c8 * 16));
        goffA[q] = (bm + r) * Hsz + c8 * 8;
    }
#pragma unroll
    for (int q = 0; q < 2; q++) {
        int rr = r0 + q * 32;
        soffW[q] = swz((u32)(rr * 128 + c8 * 16));
        goffW[q] = (n * 64 + rr) * K0 + c8 * 8;
    }

    float* sWo = reinterpret_cast<float*>(smem + OFF_WOUT);
    float* sPred = reinterpret_cast<float*>(smem + OFF_SPRED);
    for (int i = tid; i < 512; i += NTHR) sWo[i] = Wout[i];

    // ---- resident W1 (16 tiles) ----
#pragma unroll
    for (int q = 0; q < 32; q++) {
        int u = tid + q * NTHR;
        int tile = u >> 9, w = u & 511, rr = w >> 3, cc = w & 7;
        cpa16(sb + OFF_W1R + tile * 8192 + swz((u32)(rr * 128 + cc * 16)),
              d_W1f + (long)(n * 64 + rr) * K1 + tile * 64 + cc * 8);
    }
    CP_COMMIT(); CP_WAIT0();
    __syncthreads();

    float acc[2][4][4];
    float c0r[2][4], c1r[2][4];
#pragma unroll
    for (int mf = 0; mf < 2; mf++)
#pragma unroll
        for (int nf = 0; nf < 4; nf++) { c0r[mf][nf] = 0.f; c1r[mf][nf] = 0.f; }

    // stage chunk c of step tt into slot (tt + c) & 3.
    // chunk c: 0..7 = h0_old (+W0 tile c+1) ; 8 = feature (A via STS, W0 tile 0)
    //          9..16 = h1_old ; 17..24 = h0_new
    auto stageChunk = [&](int c, int tt) {
        u32 slot = (u32)((tt + c) & 3);
        if (c != 8) {
            u32 baseA = sb + OFF_A + slot * 16384;
            const __half* src;
            int kc;
            if (c < 8)       { src = d_h0[tt & 1];       kc = c * 64; }
            else if (c < 17) { src = d_h1[tt & 1];       kc = (c - 9) * 64; }
            else             { src = d_h0[(tt & 1) ^ 1]; kc = (c - 17) * 64; }
#pragma unroll
            for (int q = 0; q < 4; q++)
                cpa16(baseA + soffA[q], src + kc + goffA[q]);
        }
        if (c <= 8) {
            int wt = (c == 8) ? 0 : (c + 1);
            u32 baseW = sb + OFF_W0S + slot * 8192;
#pragma unroll
            for (int q = 0; q < 2; q++)
                cpa16(baseW + soffW[q], d_W0f + wt * 64 + goffW[q]);
        }
        CP_COMMIT();
    };
    auto mma_tiles = [&](u32 aB, u32 wB) {
#pragma unroll
        for (int kkl = 0; kkl < 4; kkl++) {
            const u32 a_sw = aswz0 ^ (u32)(kkl * 32);
            const u32 b_sw = bswz0 ^ (u32)(kkl * 32);
            u32 ah[2][4], bh[8];
#pragma unroll
            for (int mf = 0; mf < 2; mf++)
                ldsm4(aB + a_sw + mf * 2048, ah[mf][0], ah[mf][1], ah[mf][2], ah[mf][3]);
            ldsm4(wB + b_sw,        bh[0], bh[1], bh[2], bh[3]);
            ldsm4(wB + b_sw + 2048, bh[4], bh[5], bh[6], bh[7]);
#pragma unroll
            for (int mf = 0; mf < 2; mf++)
#pragma unroll
                for (int nf = 0; nf < 4; nf++)
                    mma16816(&acc[mf][nf][0], ah[mf], bh[nf * 2], bh[nf * 2 + 1]);
        }
    };
    auto epilogue = [&](float cre[2][4], const float4* bia, __half* __restrict__ hdst) {
        const bool od = (lane & 1);
        const int rbase = warp_m + (lane >> 2) + (od ? 8 : 0);
#pragma unroll
        for (int mf = 0; mf < 2; mf++)
#pragma unroll
            for (int nf = 0; nf < 4; nf++) {
                float d0 = acc[mf][nf][0], d1 = acc[mf][nf][1];
                float d2 = acc[mf][nf][2], d3 = acc[mf][nf][3];
                float v1 = __shfl_xor_sync(0xffffffffu, od ? d0 : d2, 1);
                float v2 = __shfl_xor_sync(0xffffffffu, od ? d1 : d3, 1);
                float gi = od ? v1 : d0;
                float gf = od ? v2 : d1;
                float gg = od ? d2 : v1;
                float go = od ? d3 : v2;
                float iv = fsig(gi + bia[nf].x);
                float fv = fsig(gf + bia[nf].y);
                float gv = ftanh(gg + bia[nf].z);
                float ov = fsig(go + bia[nf].w);
                float cn = fv * cre[mf][nf] + iv * gv;
                cre[mf][nf] = cn;
                int row = rbase + mf * 16;
                int col = n * 16 + jl0 + nf * 2;
                hdst[(long)(bm + row) * Hsz + col] = __float2half_rn(ov * ftanh(cn));
            }
    };
    auto barwait = [&](unsigned* ctr, unsigned target) {
        if (tid == 0) {
            unsigned cur;
            do {
                asm volatile("ld.acquire.gpu.u32 %0, [%1];"
                             : "=r"(cur) : "l"(ctr) : "memory");
            } while (cur < target);
        }
        __syncthreads();
    };
    auto arrive = [&](unsigned* ctr) {
        __syncthreads();
        if (tid == 0) {
            unsigned old, one = 1u;
            asm volatile("atom.release.gpu.add.u32 %0, [%1], %2;"
                         : "=r"(old) : "l"(ctr), "r"(one) : "memory");
        }
    };
    auto lazy_out = [&](const __half* __restrict__ h1s, int tw) {
        if (wid < 4) {
            int row = n * 4 + wid;
            const uint4* hp = reinterpret_cast<const uint4*>(h1s + (long)(bm + row) * Hsz);
            float sv = 0.f;
#pragma unroll
            for (int h8 = 0; h8 < 2; h8++) {
                uint4 vv = hp[lane * 2 + h8];
                const __half2* pp = reinterpret_cast<const __half2*>(&vv);
#pragma unroll
                for (int q = 0; q < 4; q++) {
                    float2 f2 = __half22float2(pp[q]);
                    int base = lane * 16 + h8 * 8 + q * 2;
                    sv += f2.x * sWo[base] + f2.y * sWo[base + 1];
                }
            }
#pragma unroll
            for (int o = 16; o > 0; o >>= 1) sv += __shfl_down_sync(0xffffffffu, sv, o);
            if (lane == 0) out[(long)(bm + row) * Ssz + tw] = sv + bout0;
        }
    };

    // prologue: stage chunks 0,1,2 of step 0 (3 groups in flight)
    stageChunk(0, 0);
    stageChunk(1, 0);
    stageChunk(2, 0);

#pragma unroll 1
    for (int t = 0; t < Ssz; t++) {
        const bool fb = (((t / WEEK) & 1) == 1);
        const __half* h1s = d_h1[t & 1];
        __half* h0d = d_h0[(t & 1) ^ 1];
        __half* h1d = d_h1[(t & 1) ^ 1];

#pragma unroll 1
        for (int g = 0; g < 25; g++) {
            const u32 slot = (u32)((t + g) & 3);
            const u32 aB = sb + OFF_A + slot * 16384;
            CP_WAIT2();
            if (g == 8) {
                if (fb) {   // predictions for step t-1 (h1s ready: barB waited at g==6)
                    int r = tid >> 1, hf = tid & 1;
                    const uint4* hp = reinterpret_cast<const uint4*>(
                        h1s + (long)(bm + r) * Hsz) + hf * 32;
                    float sv = 0.f;
#pragma unroll 8
                    for (int i = 0; i < 32; i++) {
                        uint4 vv = hp[i];
                        const __half2* pp = reinterpret_cast<const __half2*>(&vv);
#pragma unroll
                        for (int q = 0; q < 4; q++) {
                            float2 f2 = __half22float2(pp[q]);
                            int base = hf * 256 + i * 8 + q * 2;
                            sv += f2.x * sWo[base] + f2.y * sWo[base + 1];
                        }
                    }
                    sv += __shfl_xor_sync(0xffffffffu, sv, 1);
                    if (hf == 0) {
                        float val = sv + bout0;
                        sPred[r] = val;
                        if ((r >> 2) == n) out[(long)(bm + r) * Ssz + (t - 1)] = val;
                    }
                    __syncthreads();
                }
                // stage features (STS) into this chunk's A slot
#pragma unroll
                for (int q = 0; q < 4; q++) {
                    int r = r0 + q * 32;
                    __align__(16) __half hv[8];
                    if (c8 < 4) {
                        const float* xr = x + ((long)(bm + r) * Ssz + t) * 32 + c8 * 8;
#pragma unroll
                        for (int i = 0; i < 8; i++) {
                            float v = xr[i];
                            if (c8 == 0 && i == 0 && fb) v = sPred[r];
                            hv[i] = __float2half_rn(v);
                        }
                    } else {
#pragma unroll
                        for (int i = 0; i < 8; i++) hv[i] = __ushort_as_half(0);
                        if (c8 == 4) hv[0] = __float2half_rn(fb ? 1.f : 0.f);
                    }
                    *reinterpret_cast<uint4*>(smem + (aB - sb) + soffA[q]) =
                        *reinterpret_cast<uint4*>(hv);
                }
            }
            __syncthreads();

            if (g == 0 || g == 9) {
#pragma unroll
                for (int mf = 0; mf < 2; mf++)
#pragma unroll
                    for (int nf = 0; nf < 4; nf++)
#pragma unroll
                        for (int q = 0; q < 4; q++) acc[mf][nf][q] = 0.f;
            }

            const u32 wB = (g <= 8)  ? sb + OFF_W0S + slot * 8192
                         : (g <= 16) ? sb + OFF_W1R + (g - 1) * 8192
                                     : sb + OFF_W1R + (g - 17) * 8192;
            mma_tiles(aB, wB);

            if (g == 6 && t > 0) {
                barwait(&d_barB[mrow], 32u * (u32)t);
                if (!fb) lazy_out(h1s, t - 1);
            }
            if (g == 14) barwait(&d_barA[mrow], 32u * (u32)(t + 1));

            // stage chunk g+3 (wraps into next step for g >= 22)
            {
                int cn = g + 3, tn = t;
                if (cn >= 25) { cn -= 25; tn = t + 1; }
                stageChunk(cn, tn);
            }

            if (g == 8) {
                epilogue(c0r, bia0, h0d);
                arrive(&d_barA[mrow]);
            }
            if (g == 24) {
                epilogue(c1r, bia1, h1d);
                arrive(&d_barB[mrow]);
            }
        }
    }

    // final output column (t = Ssz-1)
    CP_WAIT0();
    barwait(&d_barB[mrow], 32u * (u32)Ssz);
    lazy_out(d_h1[Ssz & 1], Ssz - 1);
}

// ---------------- launch ------------------------------------------------------
extern "C" void kernel_launch(void* const* d_in, const int* in_sizes, int n_in,
                              void* d_out, int out_size) {
    const float* x    = (const float*)d_in[0];
    const float* Wih0 = (const float*)d_in[1];
    const float* Whh0 = (const float*)d_in[2];
    const float* bih0 = (const float*)d_in[3];
    const float* bhh0 = (const float*)d_in[4];
    const float* Wih1 = (const float*)d_in[5];
    const float* Whh1 = (const float*)d_in[6];
    const float* bih1 = (const float*)d_in[7];
    const float* bhh1 = (const float*)d_in[8];
    const float* Wout = (const float*)d_in[9];
    const float* bout = (const float*)d_in[10];
    float* out = (float*)d_out;

    cudaFuncSetAttribute(run_all, cudaFuncAttributeMaxDynamicSharedMemorySize, SMEM_BYTES);
    init_all<<<1024, 256>>>(Wih0, Whh0, bih0, bhh0, Wih1, Whh1, bih1, bhh1);
    run_all<<<dim3(Gn, Gm), NTHR, SMEM_BYTES>>>(x, Wout, bout, out);
}

// round 14
// speedup vs baseline: 1.4057x; 1.2868x over previous
#include <cuda_runtime.h>
#include <cuda_fp16.h>

typedef unsigned long long u64;
typedef unsigned int u32;

#define Bsz  512
#define Ssz  2688
#define WEEK 672
#define Hsz  512
#define Gn   32
#define Gm   4
#define NTHR 256
#define K0   576
#define K1   1024

// ---- smem layout (bytes) ----
#define OFF_W1R   0             // 16 tiles x 8KB = 131072 (resident)
#define OFF_A     131072        // 2 pair-slots x 32768 = 65536
#define OFF_W0S   196608        // 2 pair-slots x 16384 = 32768
#define OFF_WOUT  229376        // 512 f32 = 2048
#define OFF_SPRED 231424        // 128 f32 = 512
#define SMEM_BYTES 231936

// ---------------- persistent device state (no allocation) -------------------
__device__ __half d_W0f[2048 * K0];
__device__ __half d_W1f[2048 * K1];
__device__ __half d_h0[2][Bsz * Hsz];
__device__ __half d_h1[2][Bsz * Hsz];
__device__ float  d_bs0[2048], d_bs1[2048];     // permuted gc' = j*4+g
__device__ unsigned d_barA[Gm], d_barB[Gm];

__device__ __forceinline__ u32 swz(u32 off) { return off ^ ((off >> 3) & 0x70); }
__device__ __forceinline__ float fsig(float x) {
    return __fdividef(1.f, 1.f + __expf(-x));
}
__device__ __forceinline__ float ftanh(float x) {
    float e = __expf(-2.f * x);
    return __fdividef(1.f - e, 1.f + e);
}

__device__ __forceinline__ void ldsm4(u32 a, u32& r0, u32& r1, u32& r2, u32& r3) {
    asm volatile("ldmatrix.sync.aligned.m8n8.x4.shared.b16 {%0,%1,%2,%3}, [%4];"
                 : "=r"(r0), "=r"(r1), "=r"(r2), "=r"(r3) : "r"(a));
}
__device__ __forceinline__ void mma16816(float* d, const u32* a, u32 b0, u32 b1) {
    asm volatile(
        "mma.sync.aligned.m16n8k16.row.col.f32.f16.f16.f32 "
        "{%0,%1,%2,%3}, {%4,%5,%6,%7}, {%8,%9}, {%0,%1,%2,%3};"
        : "+f"(d[0]), "+f"(d[1]), "+f"(d[2]), "+f"(d[3])
        : "r"(a[0]), "r"(a[1]), "r"(a[2]), "r"(a[3]), "r"(b0), "r"(b1));
}
__device__ __forceinline__ void cpa16(u32 dst, const void* src) {
    asm volatile("cp.async.cg.shared.global [%0], [%1], 16;" :: "r"(dst), "l"(src));
}
#define CP_COMMIT() asm volatile("cp.async.commit_group;" ::: "memory")
#define CP_WAIT0()  asm volatile("cp.async.wait_group 0;" ::: "memory")

// ---------------- init --------------------------------------------------------
__global__ void init_all(const float* __restrict__ Wih0, const float* __restrict__ Whh0,
                         const float* __restrict__ bih0, const float* __restrict__ bhh0,
                         const float* __restrict__ Wih1, const float* __restrict__ Whh1,
                         const float* __restrict__ bih1, const float* __restrict__ bhh1) {
    long i0 = (long)blockIdx.x * blockDim.x + threadIdx.x;
    long stride = (long)gridDim.x * blockDim.x;
    for (long i = i0; i < 2048L * K0; i += stride) {
        int gc = (int)(i / K0), k = (int)(i % K0);
        int j = gc >> 2, g = gc & 3, row = g * 512 + j;
        float w = 0.f;
        if (k < 33)       w = Wih0[row * 33 + k];
        else if (k >= 64) w = Whh0[row * 512 + (k - 64)];
        d_W0f[i] = __float2half_rn(w);
    }
    for (long i = i0; i < 2048L * K1; i += stride) {
        int gc = (int)(i / K1), k = (int)(i % K1);
        int j = gc >> 2, g = gc & 3, row = g * 512 + j;
        float w = (k < 512) ? Wih1[row * 512 + k] : Whh1[row * 512 + (k - 512)];
        d_W1f[i] = __float2half_rn(w);
    }
    for (long i = i0; i < 2048; i += stride) {
        int j = (int)(i >> 2), g = (int)(i & 3), row = g * 512 + j;
        d_bs0[i] = bih0[row] + bhh0[row];
        d_bs1[i] = bih1[row] + bhh1[row];
    }
    const __half z = __float2half_rn(0.f);
    for (long i = i0; i < (long)Bsz * Hsz; i += stride) {
        d_h0[0][i] = z; d_h0[1][i] = z; d_h1[0][i] = z; d_h1[1][i] = z;
    }
    if (i0 < Gm) { d_barA[i0] = 0u; d_barB[i0] = 0u; }
}

// ---------------- the persistent kernel --------------------------------------
__global__ void __launch_bounds__(NTHR, 1) run_all(
    const float* __restrict__ x, const float* __restrict__ Wout,
    const float* __restrict__ bout, float* __restrict__ out) {
    extern __shared__ __align__(128) char smem[];
    const int tid = threadIdx.x, wid = tid >> 5, lane = tid & 31;
    const int n = blockIdx.x, mrow = blockIdx.y;
    const int bm = mrow * 128;
    const u32 sb = (u32)__cvta_generic_to_shared(smem);
    const float bout0 = bout[0];

    const int warp_m = (wid >> 1) * 32;          // 4 m-groups of 32 rows
    const int warp_n = (wid & 1) * 32;           // 2 n-groups of 32 gc
    const u32 aswz0 = swz((u32)((warp_m + (lane & 7) + ((lane >> 3) & 1) * 8) * 128
                                + (lane >> 4) * 16));
    const u32 bswz0 = swz((u32)((warp_n + (lane & 7) + (lane >> 4) * 8) * 128
                                + ((lane >> 3) & 1) * 16));
    const int jl0 = (warp_n >> 2) + ((lane & 3) >> 1);   // local j for nf=0
    float4 bia0[4], bia1[4];
#pragma unroll
    for (int nf = 0; nf < 4; nf++) {
        bia0[nf] = *reinterpret_cast<const float4*>(&d_bs0[n * 64 + (jl0 + nf * 2) * 4]);
        bia1[nf] = *reinterpret_cast<const float4*>(&d_bs1[n * 64 + (jl0 + nf * 2) * 4]);
    }

    // precomputed staging offsets (registers)
    const int c8 = tid & 7, r0 = tid >> 3;
    u32 soffA[4]; int goffA[4];
    u32 soffW[2]; int goffW[2];
#pragma unroll
    for (int q = 0; q < 4; q++) {
        int r = r0 + q * 32;
        soffA[q] = swz((u32)(r * 128 + c8 * 16));
        goffA[q] = (bm + r) * Hsz + c8 * 8;
    }
#pragma unroll
    for (int q = 0; q < 2; q++) {
        int rr = r0 + q * 32;
        soffW[q] = swz((u32)(rr * 128 + c8 * 16));
        goffW[q] = (n * 64 + rr) * K0 + c8 * 8;
    }

    float* sWo = reinterpret_cast<float*>(smem + OFF_WOUT);
    float* sPred = reinterpret_cast<float*>(smem + OFF_SPRED);
    for (int i = tid; i < 512; i += NTHR) sWo[i] = Wout[i];

    // ---- resident W1 (16 tiles) ----
#pragma unroll
    for (int q = 0; q < 32; q++) {
        int u = tid + q * NTHR;
        int tile = u >> 9, w = u & 511, rr = w >> 3, cc = w & 7;
        cpa16(sb + OFF_W1R + tile * 8192 + swz((u32)(rr * 128 + cc * 16)),
              d_W1f + (long)(n * 64 + rr) * K1 + tile * 64 + cc * 8);
    }
    CP_COMMIT(); CP_WAIT0();
    __syncthreads();

    float acc[2][4][4];
    float c0r[2][4], c1r[2][4];
#pragma unroll
    for (int mf = 0; mf < 2; mf++)
#pragma unroll
        for (int nf = 0; nf < 4; nf++) { c0r[mf][nf] = 0.f; c1r[mf][nf] = 0.f; }

    u32 sp = 0;   // parity of the pair-slot being CONSUMED this iteration

    // stage iteration j of step tt into parity sp^1.
    // j 0..3: h0_old K-pair j*128 + W0 tiles 2j+1,2j+2
    // j 4:    W0 tile 0 only (feature A is STS'd at consume time)
    // j 5..8: h1_old K-pair (j-5)*128
    // j 9..12: h0_new K-pair (j-9)*128
    auto stageIter = [&](int j, int tt) {
        u32 baseA = sb + OFF_A + (sp ^ 1u) * 32768;
        u32 baseW = sb + OFF_W0S + (sp ^ 1u) * 16384;
        if (j < 4) {
            const __half* src = d_h0[tt & 1] + j * 128;
#pragma unroll
            for (int q = 0; q < 4; q++) {
                cpa16(baseA + soffA[q],         src + goffA[q]);
                cpa16(baseA + 16384 + soffA[q], src + 64 + goffA[q]);
            }
            const __half* wsrc = d_W0f + (2 * j + 1) * 64;
#pragma unroll
            for (int q = 0; q < 2; q++) {
                cpa16(baseW + soffW[q],        wsrc + goffW[q]);
                cpa16(baseW + 8192 + soffW[q], wsrc + 64 + goffW[q]);
            }
        } else if (j == 4) {
#pragma unroll
            for (int q = 0; q < 2; q++)
                cpa16(baseW + soffW[q], d_W0f + goffW[q]);
        } else {
            const __half* src = (j < 9) ? d_h1[tt & 1] + (j - 5) * 128
                                        : d_h0[(tt & 1) ^ 1] + (j - 9) * 128;
#pragma unroll
            for (int q = 0; q < 4; q++) {
                cpa16(baseA + soffA[q],         src + goffA[q]);
                cpa16(baseA + 16384 + soffA[q], src + 64 + goffA[q]);
            }
        }
        CP_COMMIT();
    };
    auto mma_tiles = [&](u32 aB, u32 wB) {
#pragma unroll
        for (int kkl = 0; kkl < 4; kkl++) {
            const u32 a_sw = aswz0 ^ (u32)(kkl * 32);
            const u32 b_sw = bswz0 ^ (u32)(kkl * 32);
            u32 ah[2][4], bh[8];
#pragma unroll
            for (int mf = 0; mf < 2; mf++)
                ldsm4(aB + a_sw + mf * 2048, ah[mf][0], ah[mf][1], ah[mf][2], ah[mf][3]);
            ldsm4(wB + b_sw,        bh[0], bh[1], bh[2], bh[3]);
            ldsm4(wB + b_sw + 2048, bh[4], bh[5], bh[6], bh[7]);
#pragma unroll
            for (int mf = 0; mf < 2; mf++)
#pragma unroll
                for (int nf = 0; nf < 4; nf++)
                    mma16816(&acc[mf][nf][0], ah[mf], bh[nf * 2], bh[nf * 2 + 1]);
        }
    };
    auto zero_acc = [&]() {
#pragma unroll
        for (int mf = 0; mf < 2; mf++)
#pragma unroll
            for (int nf = 0; nf < 4; nf++)
#pragma unroll
                for (int q = 0; q < 4; q++) acc[mf][nf][q] = 0.f;
    };
    auto epilogue = [&](float cre[2][4], const float4* bia, __half* __restrict__ hdst) {
        const bool od = (lane & 1);
        const int rbase = warp_m + (lane >> 2) + (od ? 8 : 0);
#pragma unroll
        for (int mf = 0; mf < 2; mf++)
#pragma unroll
            for (int nf = 0; nf < 4; nf++) {
                float d0 = acc[mf][nf][0], d1 = acc[mf][nf][1];
                float d2 = acc[mf][nf][2], d3 = acc[mf][nf][3];
                float v1 = __shfl_xor_sync(0xffffffffu, od ? d0 : d2, 1);
                float v2 = __shfl_xor_sync(0xffffffffu, od ? d1 : d3, 1);
                float gi = od ? v1 : d0;
                float gf = od ? v2 : d1;
                float gg = od ? d2 : v1;
                float go = od ? d3 : v2;
                float iv = fsig(gi + bia[nf].x);
                float fv = fsig(gf + bia[nf].y);
                float gv = ftanh(gg + bia[nf].z);
                float ov = fsig(go + bia[nf].w);
                float cn = fv * cre[mf][nf] + iv * gv;
                cre[mf][nf] = cn;
                int row = rbase + mf * 16;
                int col = n * 16 + jl0 + nf * 2;
                hdst[(long)(bm + row) * Hsz + col] = __float2half_rn(ov * ftanh(cn));
            }
    };
    auto barwait = [&](unsigned* ctr, unsigned target) {
        if (tid == 0) {
            unsigned cur;
            do {
                asm volatile("ld.acquire.gpu.u32 %0, [%1];"
                             : "=r"(cur) : "l"(ctr) : "memory");
            } while (cur < target);
        }
        __syncthreads();
    };
    auto arrive = [&](unsigned* ctr) {
        __syncthreads();
        if (tid == 0) {
            unsigned old, one = 1u;
            asm volatile("atom.release.gpu.add.u32 %0, [%1], %2;"
                         : "=r"(old) : "l"(ctr), "r"(one) : "memory");
        }
    };
    auto lazy_out = [&](const __half* __restrict__ h1s, int tw) {
        if (wid < 4) {
            int row = n * 4 + wid;
            const uint4* hp = reinterpret_cast<const uint4*>(h1s + (long)(bm + row) * Hsz);
            float sv = 0.f;
#pragma unroll
            for (int h8 = 0; h8 < 2; h8++) {
                uint4 vv = hp[lane * 2 + h8];
                const __half2* pp = reinterpret_cast<const __half2*>(&vv);
#pragma unroll
                for (int q = 0; q < 4; q++) {
                    float2 f2 = __half22float2(pp[q]);
                    int base = lane * 16 + h8 * 8 + q * 2;
                    sv += f2.x * sWo[base] + f2.y * sWo[base + 1];
                }
            }
#pragma unroll
            for (int o = 16; o > 0; o >>= 1) sv += __shfl_down_sync(0xffffffffu, sv, o);
            if (lane == 0) out[(long)(bm + row) * Ssz + tw] = sv + bout0;
        }
    };

    // prologue: stage I0 of step 0 into parity 0
    sp = 1;
    stageIter(0, 0);
    sp = 0;

#pragma unroll 1
    for (int t = 0; t < Ssz; t++) {
        const bool fb = (((t / WEEK) & 1) == 1);
        const __half* h1s = d_h1[t & 1];
        __half* h0d = d_h0[(t & 1) ^ 1];
        __half* h1d = d_h1[(t & 1) ^ 1];

        zero_acc();
        // ===== I0..I3: layer-0 h0_old pairs (streamed W0) =====
#pragma unroll 1
        for (int i = 0; i < 4; i++) {
            CP_WAIT0();
            __syncthreads();
            u32 aB = sb + OFF_A + sp * 32768;
            u32 wB = sb + OFF_W0S + sp * 16384;
            stageIter(i + 1, t);
            mma_tiles(aB, wB);
            mma_tiles(aB + 16384, wB + 8192);
            if (i == 3 && t > 0) {
                barwait(&d_barB[mrow], 32u * (u32)t);
                if (!fb) lazy_out(h1s, t - 1);
            }
            sp ^= 1u;
        }
        // ===== I4: feature chunk + epilogue 0 =====
        {
            CP_WAIT0();
            __syncthreads();
            u32 aB = sb + OFF_A + sp * 32768;
            u32 wB = sb + OFF_W0S + sp * 16384;
            if (fb) {   // predictions for step t-1 (barB waited at I3)
                int r = tid >> 1, hf = tid & 1;
                const uint4* hp = reinterpret_cast<const uint4*>(
                    h1s + (long)(bm + r) * Hsz) + hf * 32;
                float sv = 0.f;
#pragma unroll 8
                for (int i = 0; i < 32; i++) {
                    uint4 vv = hp[i];
                    const __half2* pp = reinterpret_cast<const __half2*>(&vv);
#pragma unroll
                    for (int q = 0; q < 4; q++) {
                        float2 f2 = __half22float2(pp[q]);
                        int base = hf * 256 + i * 8 + q * 2;
                        sv += f2.x * sWo[base] + f2.y * sWo[base + 1];
                    }
                }
                sv += __shfl_xor_sync(0xffffffffu, sv, 1);
                if (hf == 0) {
                    float val = sv + bout0;
                    sPred[r] = val;
                    if ((r >> 2) == n) out[(long)(bm + r) * Ssz + (t - 1)] = val;
                }
                __syncthreads();
            }
            // stage features (STS) into first A slot of this parity
#pragma unroll
            for (int q = 0; q < 4; q++) {
                int r = r0 + q * 32;
                __align__(16) __half hv[8];
                if (c8 < 4) {
                    const float* xr = x + ((long)(bm + r) * Ssz + t) * 32 + c8 * 8;
#pragma unroll
                    for (int i = 0; i < 8; i++) {
                        float v = xr[i];
                        if (c8 == 0 && i == 0 && fb) v = sPred[r];
                        hv[i] = __float2half_rn(v);
                    }
                } else {
#pragma unroll
                    for (int i = 0; i < 8; i++) hv[i] = __ushort_as_half(0);
                    if (c8 == 4) hv[0] = __float2half_rn(fb ? 1.f : 0.f);
                }
                *reinterpret_cast<uint4*>(smem + (aB - sb) + soffA[q]) =
                    *reinterpret_cast<uint4*>(hv);
            }
            __syncthreads();
            stageIter(5, t);
            mma_tiles(aB, wB);
            epilogue(c0r, bia0, h0d);
            arrive(&d_barA[mrow]);
            sp ^= 1u;
        }
        // ===== I5..I8: layer-1 h1_old pairs (W1R tiles 8..15) =====
        zero_acc();
#pragma unroll 1
        for (int i = 0; i < 4; i++) {
            CP_WAIT0();
            __syncthreads();
            u32 aB = sb + OFF_A + sp * 32768;
            u32 wB = sb + OFF_W1R + (u32)(8 + 2 * i) * 8192;
            stageIter(6 + i, t);
            mma_tiles(aB, wB);
            mma_tiles(aB + 16384, wB + 8192);
            if (i == 2) barwait(&d_barA[mrow], 32u * (u32)(t + 1));
            sp ^= 1u;
        }
        // ===== I9..I12: layer-1 h0_new pairs (W1R tiles 0..7) =====
#pragma unroll 1
        for (int i = 0; i < 4; i++) {
            CP_WAIT0();
            __syncthreads();
            u32 aB = sb + OFF_A + sp * 32768;
            u32 wB = sb + OFF_W1R + (u32)(2 * i) * 8192;
            if (i < 3) stageIter(10 + i, t);
            else       stageIter(0, t + 1);
            mma_tiles(aB, wB);
            mma_tiles(aB + 16384, wB + 8192);
            sp ^= 1u;
        }
        epilogue(c1r, bia1, h1d);
        arrive(&d_barB[mrow]);
    }

    // final output column (t = Ssz-1)
    CP_WAIT0();
    barwait(&d_barB[mrow], 32u * (u32)Ssz);
    lazy_out(d_h1[Ssz & 1], Ssz - 1);
}

// ---------------- launch ------------------------------------------------------
extern "C" void kernel_launch(void* const* d_in, const int* in_sizes, int n_in,
                              void* d_out, int out_size) {
    const float* x    = (const float*)d_in[0];
    const float* Wih0 = (const float*)d_in[1];
    const float* Whh0 = (const float*)d_in[2];
    const float* bih0 = (const float*)d_in[3];
    const float* bhh0 = (const float*)d_in[4];
    const float* Wih1 = (const float*)d_in[5];
    const float* Whh1 = (const float*)d_in[6];
    const float* bih1 = (const float*)d_in[7];
    const float* bhh1 = (const float*)d_in[8];
    const float* Wout = (const float*)d_in[9];
    const float* bout = (const float*)d_in[10];
    float* out = (float*)d_out;

    cudaFuncSetAttribute(run_all, cudaFuncAttributeMaxDynamicSharedMemorySize, SMEM_BYTES);
    init_all<<<1024, 256>>>(Wih0, Whh0, bih0, bhh0, Wih1, Whh1, bih1, bhh1);
    run_all<<<dim3(Gn, Gm), NTHR, SMEM_BYTES>>>(x, Wout, bout, out);
}

// round 15
// speedup vs baseline: 1.4702x; 1.0459x over previous
#include <cuda_runtime.h>
#include <cuda_fp16.h>

typedef unsigned long long u64;
typedef unsigned int u32;

#define Bsz  512
#define Ssz  2688
#define WEEK 672
#define Hsz  512
#define Gn   32
#define Gm   4
#define NTHR 256
#define K0   576
#define K1   1024

// ---- smem layout (bytes) ----
#define OFF_A     0             // 2 quad-slots x 65536 = 131072
#define OFF_WS    131072        // 2 quad-slots x 32768 = 65536
#define OFF_WOUT  196608        // 512 f32 = 2048
#define OFF_SPRED 198656        // 128 f32 = 512
#define SMEM_BYTES 199168

// ---------------- persistent device state (no allocation) -------------------
__device__ __half d_W0f[2048 * K0];
__device__ __half d_W1f[2048 * K1];
__device__ __half d_h0[2][Bsz * Hsz];
__device__ __half d_h1[2][Bsz * Hsz];
__device__ float  d_bs0[2048], d_bs1[2048];     // permuted gc' = j*4+g
__device__ unsigned d_barA[Gm], d_barB[Gm];

__device__ __forceinline__ u32 swz(u32 off) { return off ^ ((off >> 3) & 0x70); }
__device__ __forceinline__ float fsig(float x) {
    return __fdividef(1.f, 1.f + __expf(-x));
}
__device__ __forceinline__ float ftanh(float x) {
    float e = __expf(-2.f * x);
    return __fdividef(1.f - e, 1.f + e);
}

__device__ __forceinline__ void ldsm4(u32 a, u32& r0, u32& r1, u32& r2, u32& r3) {
    asm volatile("ldmatrix.sync.aligned.m8n8.x4.shared.b16 {%0,%1,%2,%3}, [%4];"
                 : "=r"(r0), "=r"(r1), "=r"(r2), "=r"(r3) : "r"(a));
}
__device__ __forceinline__ void mma16816(float* d, const u32* a, u32 b0, u32 b1) {
    asm volatile(
        "mma.sync.aligned.m16n8k16.row.col.f32.f16.f16.f32 "
        "{%0,%1,%2,%3}, {%4,%5,%6,%7}, {%8,%9}, {%0,%1,%2,%3};"
        : "+f"(d[0]), "+f"(d[1]), "+f"(d[2]), "+f"(d[3])
        : "r"(a[0]), "r"(a[1]), "r"(a[2]), "r"(a[3]), "r"(b0), "r"(b1));
}
__device__ __forceinline__ void cpa16(u32 dst, const void* src) {
    asm volatile("cp.async.cg.shared.global [%0], [%1], 16;" :: "r"(dst), "l"(src));
}
#define CP_COMMIT() asm volatile("cp.async.commit_group;" ::: "memory")
#define CP_WAIT0()  asm volatile("cp.async.wait_group 0;" ::: "memory")

// ---------------- init --------------------------------------------------------
__global__ void init_all(const float* __restrict__ Wih0, const float* __restrict__ Whh0,
                         const float* __restrict__ bih0, const float* __restrict__ bhh0,
                         const float* __restrict__ Wih1, const float* __restrict__ Whh1,
                         const float* __restrict__ bih1, const float* __restrict__ bhh1) {
    long i0 = (long)blockIdx.x * blockDim.x + threadIdx.x;
    long stride = (long)gridDim.x * blockDim.x;
    for (long i = i0; i < 2048L * K0; i += stride) {
        int gc = (int)(i / K0), k = (int)(i % K0);
        int j = gc >> 2, g = gc & 3, row = g * 512 + j;
        float w = 0.f;
        if (k < 33)       w = Wih0[row * 33 + k];
        else if (k >= 64) w = Whh0[row * 512 + (k - 64)];
        d_W0f[i] = __float2half_rn(w);
    }
    for (long i = i0; i < 2048L * K1; i += stride) {
        int gc = (int)(i / K1), k = (int)(i % K1);
        int j = gc >> 2, g = gc & 3, row = g * 512 + j;
        float w = (k < 512) ? Wih1[row * 512 + k] : Whh1[row * 512 + (k - 512)];
        d_W1f[i] = __float2half_rn(w);
    }
    for (long i = i0; i < 2048; i += stride) {
        int j = (int)(i >> 2), g = (int)(i & 3), row = g * 512 + j;
        d_bs0[i] = bih0[row] + bhh0[row];
        d_bs1[i] = bih1[row] + bhh1[row];
    }
    const __half z = __float2half_rn(0.f);
    for (long i = i0; i < (long)Bsz * Hsz; i += stride) {
        d_h0[0][i] = z; d_h0[1][i] = z; d_h1[0][i] = z; d_h1[1][i] = z;
    }
    if (i0 < Gm) { d_barA[i0] = 0u; d_barB[i0] = 0u; }
}

// ---------------- the persistent kernel --------------------------------------
__global__ void __launch_bounds__(NTHR, 1) run_all(
    const float* __restrict__ x, const float* __restrict__ Wout,
    const float* __restrict__ bout, float* __restrict__ out) {
    extern __shared__ __align__(128) char smem[];
    const int tid = threadIdx.x, wid = tid >> 5, lane = tid & 31;
    const int n = blockIdx.x, mrow = blockIdx.y;
    const int bm = mrow * 128;
    const u32 sb = (u32)__cvta_generic_to_shared(smem);
    const float bout0 = bout[0];

    const int warp_m = (wid >> 1) * 32;          // 4 m-groups of 32 rows
    const int warp_n = (wid & 1) * 32;           // 2 n-groups of 32 gc
    const u32 aswz0 = swz((u32)((warp_m + (lane & 7) + ((lane >> 3) & 1) * 8) * 128
                                + (lane >> 4) * 16));
    const u32 bswz0 = swz((u32)((warp_n + (lane & 7) + (lane >> 4) * 8) * 128
                                + ((lane >> 3) & 1) * 16));
    const int jl0 = (warp_n >> 2) + ((lane & 3) >> 1);   // local j for nf=0
    float4 bia0[4], bia1[4];
#pragma unroll
    for (int nf = 0; nf < 4; nf++) {
        bia0[nf] = *reinterpret_cast<const float4*>(&d_bs0[n * 64 + (jl0 + nf * 2) * 4]);
        bia1[nf] = *reinterpret_cast<const float4*>(&d_bs1[n * 64 + (jl0 + nf * 2) * 4]);
    }

    // precomputed staging offsets (registers)
    const int c8 = tid & 7, r0 = tid >> 3;
    u32 soffA[4]; int goffA[4];
    u32 soffW[2]; int goffW0[2], goffW1[2];
#pragma unroll
    for (int q = 0; q < 4; q++) {
        int r = r0 + q * 32;
        soffA[q] = swz((u32)(r * 128 + c8 * 16));
        goffA[q] = (bm + r) * Hsz + c8 * 8;
    }
#pragma unroll
    for (int q = 0; q < 2; q++) {
        int rr = r0 + q * 32;
        soffW[q] = swz((u32)(rr * 128 + c8 * 16));
        goffW0[q] = (n * 64 + rr) * K0 + c8 * 8;
        goffW1[q] = (n * 64 + rr) * K1 + c8 * 8;
    }

    float* sWo = reinterpret_cast<float*>(smem + OFF_WOUT);
    float* sPred = reinterpret_cast<float*>(smem + OFF_SPRED);
    for (int i = tid; i < 512; i += NTHR) sWo[i] = Wout[i];
    __syncthreads();

    float acc[2][4][4];
    float c0r[2][4], c1r[2][4];
#pragma unroll
    for (int mf = 0; mf < 2; mf++)
#pragma unroll
        for (int nf = 0; nf < 4; nf++) { c0r[mf][nf] = 0.f; c1r[mf][nf] = 0.f; }

    u32 sp = 0;   // parity of the quad-slot being CONSUMED this iteration

    // stage iteration j of step tt into parity sp^1 (K=256 quads).
    // j0: h0_old[0:256) x W0 k[64:320)    j1: h0_old[256:512) x W0 k[320:576)
    // j2: feature (A via STS later) + W0 k[0:64) subtile only
    // j3: h1_old[0:256) x W1 k[512:768)   j4: h1_old[256:512) x W1 k[768:1024)
    // j5: h0_new[0:256) x W1 k[0:256)     j6: h0_new[256:512) x W1 k[256:512)
    auto stageJ = [&](int j, int tt) {
        u32 aB = sb + OFF_A + (sp ^ 1u) * 65536;
        u32 wB = sb + OFF_WS + (sp ^ 1u) * 32768;
        if (j == 2) {
#pragma unroll
            for (int q = 0; q < 2; q++)
                cpa16(wB + soffW[q], d_W0f + goffW0[q]);
        } else {
            const __half* asrc;
            const __half* wsrc;
            bool w0 = false;
            switch (j) {
                case 0: asrc = d_h0[tt & 1];             wsrc = d_W0f + 64;  w0 = true; break;
                case 1: asrc = d_h0[tt & 1] + 256;       wsrc = d_W0f + 320; w0 = true; break;
                case 3: asrc = d_h1[tt & 1];             wsrc = d_W1f + 512; break;
                case 4: asrc = d_h1[tt & 1] + 256;       wsrc = d_W1f + 768; break;
                case 5: asrc = d_h0[(tt & 1) ^ 1];       wsrc = d_W1f;       break;
                default: asrc = d_h0[(tt & 1) ^ 1] + 256; wsrc = d_W1f + 256; break;
            }
#pragma unroll
            for (int s = 0; s < 4; s++) {
#pragma unroll
                for (int q = 0; q < 4; q++)
                    cpa16(aB + s * 16384 + soffA[q], asrc + s * 64 + goffA[q]);
#pragma unroll
                for (int q = 0; q < 2; q++)
                    cpa16(wB + s * 8192 + soffW[q],
                          wsrc + s * 64 + (w0 ? goffW0[q] : goffW1[q]));
            }
        }
        CP_COMMIT();
    };
    auto mma_tiles = [&](u32 aB, u32 wB) {
#pragma unroll
        for (int kkl = 0; kkl < 4; kkl++) {
            const u32 a_sw = aswz0 ^ (u32)(kkl * 32);
            const u32 b_sw = bswz0 ^ (u32)(kkl * 32);
            u32 ah[2][4], bh[8];
#pragma unroll
            for (int mf = 0; mf < 2; mf++)
                ldsm4(aB + a_sw + mf * 2048, ah[mf][0], ah[mf][1], ah[mf][2], ah[mf][3]);
            ldsm4(wB + b_sw,        bh[0], bh[1], bh[2], bh[3]);
            ldsm4(wB + b_sw + 2048, bh[4], bh[5], bh[6], bh[7]);
#pragma unroll
            for (int mf = 0; mf < 2; mf++)
#pragma unroll
                for (int nf = 0; nf < 4; nf++)
                    mma16816(&acc[mf][nf][0], ah[mf], bh[nf * 2], bh[nf * 2 + 1]);
        }
    };
    auto mma_quad = [&](u32 aB, u32 wB) {
#pragma unroll
        for (int s = 0; s < 4; s++)
            mma_tiles(aB + (u32)s * 16384, wB + (u32)s * 8192);
    };
    auto zero_acc = [&]() {
#pragma unroll
        for (int mf = 0; mf < 2; mf++)
#pragma unroll
            for (int nf = 0; nf < 4; nf++)
#pragma unroll
                for (int q = 0; q < 4; q++) acc[mf][nf][q] = 0.f;
    };
    auto epilogue = [&](float cre[2][4], const float4* bia, __half* __restrict__ hdst) {
        const bool od = (lane & 1);
        const int rbase = warp_m + (lane >> 2) + (od ? 8 : 0);
#pragma unroll
        for (int mf = 0; mf < 2; mf++)
#pragma unroll
            for (int nf = 0; nf < 4; nf++) {
                float d0 = acc[mf][nf][0], d1 = acc[mf][nf][1];
                float d2 = acc[mf][nf][2], d3 = acc[mf][nf][3];
                float v1 = __shfl_xor_sync(0xffffffffu, od ? d0 : d2, 1);
                float v2 = __shfl_xor_sync(0xffffffffu, od ? d1 : d3, 1);
                float gi = od ? v1 : d0;
                float gf = od ? v2 : d1;
                float gg = od ? d2 : v1;
                float go = od ? d3 : v2;
                float iv = fsig(gi + bia[nf].x);
                float fv = fsig(gf + bia[nf].y);
                float gv = ftanh(gg + bia[nf].z);
                float ov = fsig(go + bia[nf].w);
                float cn = fv * cre[mf][nf] + iv * gv;
                cre[mf][nf] = cn;
                int row = rbase + mf * 16;
                int col = n * 16 + jl0 + nf * 2;
                hdst[(long)(bm + row) * Hsz + col] = __float2half_rn(ov * ftanh(cn));
            }
    };
    auto barwait = [&](unsigned* ctr, unsigned target) {
        if (tid == 0) {
            unsigned cur;
            do {
                asm volatile("ld.acquire.gpu.u32 %0, [%1];"
                             : "=r"(cur) : "l"(ctr) : "memory");
            } while (cur < target);
        }
        __syncthreads();
    };
    auto arrive = [&](unsigned* ctr) {
        __syncthreads();
        if (tid == 0) {
            unsigned old, one = 1u;
            asm volatile("atom.release.gpu.add.u32 %0, [%1], %2;"
                         : "=r"(old) : "l"(ctr), "r"(one) : "memory");
        }
    };
    auto lazy_out = [&](const __half* __restrict__ h1s, int tw) {
        if (wid < 4) {
            int row = n * 4 + wid;
            const uint4* hp = reinterpret_cast<const uint4*>(h1s + (long)(bm + row) * Hsz);
            float sv = 0.f;
#pragma unroll
            for (int h8 = 0; h8 < 2; h8++) {
                uint4 vv = hp[lane * 2 + h8];
                const __half2* pp = reinterpret_cast<const __half2*>(&vv);
#pragma unroll
                for (int q = 0; q < 4; q++) {
                    float2 f2 = __half22float2(pp[q]);
                    int base = lane * 16 + h8 * 8 + q * 2;
                    sv += f2.x * sWo[base] + f2.y * sWo[base + 1];
                }
            }
#pragma unroll
            for (int o = 16; o > 0; o >>= 1) sv += __shfl_down_sync(0xffffffffu, sv, o);
            if (lane == 0) out[(long)(bm + row) * Ssz + tw] = sv + bout0;
        }
    };

    // prologue: stage J0 of step 0 into parity 0
    sp = 1;
    stageJ(0, 0);
    sp = 0;

#pragma unroll 1
    for (int t = 0; t < Ssz; t++) {
        const bool fb = (((t / WEEK) & 1) == 1);
        const __half* h1s = d_h1[t & 1];
        __half* h0d = d_h0[(t & 1) ^ 1];
        __half* h1d = d_h1[(t & 1) ^ 1];

        zero_acc();
        // ===== J0: h0_old[0:256) =====
        CP_WAIT0();
        __syncthreads();
        {
            u32 aB = sb + OFF_A + sp * 65536, wB = sb + OFF_WS + sp * 32768;
            stageJ(1, t);
            mma_quad(aB, wB);
            sp ^= 1u;
        }
        // ===== J1: h0_old[256:512) =====
        CP_WAIT0();
        __syncthreads();
        {
            u32 aB = sb + OFF_A + sp * 65536, wB = sb + OFF_WS + sp * 32768;
            stageJ(2, t);
            mma_quad(aB, wB);
            if (t > 0) {
                barwait(&d_barB[mrow], 32u * (u32)t);
                if (!fb) lazy_out(h1s, t - 1);
            }
            sp ^= 1u;
        }
        // ===== J2: feature chunk + epilogue 0 =====
        CP_WAIT0();
        __syncthreads();
        {
            u32 aB = sb + OFF_A + sp * 65536, wB = sb + OFF_WS + sp * 32768;
            if (fb) {   // predictions for step t-1 (barB waited at J1)
                int r = tid >> 1, hf = tid & 1;
                const uint4* hp = reinterpret_cast<const uint4*>(
                    h1s + (long)(bm + r) * Hsz) + hf * 32;
                float sv = 0.f;
#pragma unroll 8
                for (int i = 0; i < 32; i++) {
                    uint4 vv = hp[i];
                    const __half2* pp = reinterpret_cast<const __half2*>(&vv);
#pragma unroll
                    for (int q = 0; q < 4; q++) {
                        float2 f2 = __half22float2(pp[q]);
                        int base = hf * 256 + i * 8 + q * 2;
                        sv += f2.x * sWo[base] + f2.y * sWo[base + 1];
                    }
                }
                sv += __shfl_xor_sync(0xffffffffu, sv, 1);
                if (hf == 0) {
                    float val = sv + bout0;
                    sPred[r] = val;
                    if ((r >> 2) == n) out[(long)(bm + r) * Ssz + (t - 1)] = val;
                }
                __syncthreads();
            }
            // stage features (STS) into subtile 0 of this parity's A slot
#pragma unroll
            for (int q = 0; q < 4; q++) {
                int r = r0 + q * 32;
                __align__(16) __half hv[8];
                if (c8 < 4) {
                    const float* xr = x + ((long)(bm + r) * Ssz + t) * 32 + c8 * 8;
#pragma unroll
                    for (int i = 0; i < 8; i++) {
                        float v = xr[i];
                        if (c8 == 0 && i == 0 && fb) v = sPred[r];
                        hv[i] = __float2half_rn(v);
                    }
                } else {
#pragma unroll
                    for (int i = 0; i < 8; i++) hv[i] = __ushort_as_half(0);
                    if (c8 == 4) hv[0] = __float2half_rn(fb ? 1.f : 0.f);
                }
                *reinterpret_cast<uint4*>(smem + (aB - sb) + soffA[q]) =
                    *reinterpret_cast<uint4*>(hv);
            }
            __syncthreads();
            stageJ(3, t);
            mma_tiles(aB, wB);          // K=64 feature subtile only
            epilogue(c0r, bia0, h0d);
            arrive(&d_barA[mrow]);
            sp ^= 1u;
        }
        zero_acc();
        // ===== J3: h1_old[0:256) =====
        CP_WAIT0();
        __syncthreads();
        {
            u32 aB = sb + OFF_A + sp * 65536, wB = sb + OFF_WS + sp * 32768;
            stageJ(4, t);
            mma_quad(aB, wB);
            barwait(&d_barA[mrow], 32u * (u32)(t + 1));
            sp ^= 1u;
        }
        // ===== J4: h1_old[256:512) =====
        CP_WAIT0();
        __syncthreads();
        {
            u32 aB = sb + OFF_A + sp * 65536, wB = sb + OFF_WS + sp * 32768;
            stageJ(5, t);               // h0_new — after barA ✓
            mma_quad(aB, wB);
            sp ^= 1u;
        }
        // ===== J5: h0_new[0:256) =====
        CP_WAIT0();
        __syncthreads();
        {
            u32 aB = sb + OFF_A + sp * 65536, wB = sb + OFF_WS + sp * 32768;
            stageJ(6, t);
            mma_quad(aB, wB);
            sp ^= 1u;
        }
        // ===== J6: h0_new[256:512) + epilogue 1 =====
        CP_WAIT0();
        __syncthreads();
        {
            u32 aB = sb + OFF_A + sp * 65536, wB = sb + OFF_WS + sp * 32768;
            stageJ(0, t + 1);           // h0_old of t+1 = h0d (ready since J2)
            mma_quad(aB, wB);
            epilogue(c1r, bia1, h1d);
            arrive(&d_barB[mrow]);
            sp ^= 1u;
        }
    }

    // final output column (t = Ssz-1)
    CP_WAIT0();
    barwait(&d_barB[mrow], 32u * (u32)Ssz);
    lazy_out(d_h1[Ssz & 1], Ssz - 1);
}

// ---------------- launch ------------------------------------------------------
extern "C" void kernel_launch(void* const* d_in, const int* in_sizes, int n_in,
                              void* d_out, int out_size) {
    const float* x    = (const float*)d_in[0];
    const float* Wih0 = (const float*)d_in[1];
    const float* Whh0 = (const float*)d_in[2];
    const float* bih0 = (const float*)d_in[3];
    const float* bhh0 = (const float*)d_in[4];
    const float* Wih1 = (const float*)d_in[5];
    const float* Whh1 = (const float*)d_in[6];
    const float* bih1 = (const float*)d_in[7];
    const float* bhh1 = (const float*)d_in[8];
    const float* Wout = (const float*)d_in[9];
    const float* bout = (const float*)d_in[10];
    float* out = (float*)d_out;

    cudaFuncSetAttribute(run_all, cudaFuncAttributeMaxDynamicSharedMemorySize, SMEM_BYTES);
    init_all<<<1024, 256>>>(Wih0, Whh0, bih0, bhh0, Wih1, Whh1, bih1, bhh1);
    run_all<<<dim3(Gn, Gm), NTHR, SMEM_BYTES>>>(x, Wout, bout, out);
}